// round 15
// baseline (speedup 1.0000x reference)
#include <cuda_runtime.h>
#include <cuda_bf16.h>
#include <stdint.h>

// Fused gather-concat:
//   out[r, 0:8]  = proc_pos[process_ids[r], :]   (16x8 f32 -> smem, transposed)
//   out[r, 8:11] = locs_sp[location_ids[r], :]   (500000x3 f32 -> padded float4 table)
//
// R15: flush via TMA bulk store. The staged 1408B warp tile is written to GMEM
// with cp.async.bulk.global.shared::cta (async proxy: NO flush-LDS, NO STG in
// l1tex ~= -23 cyc/tile of the ~112 l1tex budget). Double-buffered warp
// stage slots, bulk_group wait depth 1, fence.proxy.async before each issue.
// Gather stays LDG.128 (per-lane TMA gather would be ELECT-serialized: worse).
// Keeps: R13 two-stage id/gather pipeline (regs pinned 32 via launch_bounds),
// transposed scalar proc table, lane-stride-11 STS, persistent warps.

#define THREADS 256
#define WARPS (THREADS / 32)
#define PROC_DIM 8
#define SP_DIM 3
#define OUT_DIM 11
#define MAX_LOCS 500000
#define TILE 32
#define TILE_BYTES (TILE * OUT_DIM * 4)   // 1408

__device__ int g_ids_are_i64;
__device__ float4 g_locs_pad[MAX_LOCS];   // 8 MB static scratch

__global__ __launch_bounds__(256)
void setup_kernel(const float* __restrict__ locs_sp, int num_locs,
                  const int* __restrict__ loc_ids_w, int naug)
{
    int i = blockIdx.x * blockDim.x + threadIdx.x;
    if (i < num_locs) {
        const float* s = locs_sp + (size_t)i * SP_DIM;
        float4 v;
        v.x = s[0]; v.y = s[1]; v.z = s[2]; v.w = 0.0f;
        g_locs_pad[i] = v;
    }
    // int64 little-endian ids with values < 5e5 look like (v,0,v,0,...):
    // every odd 32-bit word is zero. Random int32: P(64 zeros) ~ 0.
    if (blockIdx.x == 0) {
        __shared__ int s_not64;
        if (threadIdx.x == 0) s_not64 = 0;
        __syncthreads();
        int n_check = naug < 64 ? naug : 64;
        if (threadIdx.x < n_check) {
            if (loc_ids_w[2 * threadIdx.x + 1] != 0) atomicOr(&s_not64, 1);
        }
        __syncthreads();
        if (threadIdx.x == 0) g_ids_are_i64 = s_not64 ? 0 : 1;
    }
}

// Load ids for one row, clamp, pack: (pid << 20) | lid  (lid < 2^20).
__device__ __forceinline__ int load_ids_packed(
    const void* process_ids, const void* location_ids,
    int row, int naug, int ids64, int num_procs, int num_locs)
{
    int rp = 0, rl = 0;
    if (row < naug) {
        if (ids64) {
            rp = (int)__ldcs(&((const long long*)process_ids)[row]);
            rl = (int)__ldcs(&((const long long*)location_ids)[row]);
        } else {
            rp = __ldcs(&((const int*)process_ids)[row]);
            rl = __ldcs(&((const int*)location_ids)[row]);
        }
    }
    rp = min(max(rp, 0), num_procs - 1);
    rl = min(max(rl, 0), num_locs - 1);
    return (rp << 20) | rl;
}

__global__ __launch_bounds__(THREADS, 8)
void gather_concat_kernel(
    const float* __restrict__ proc_pos,
    const void*  __restrict__ process_ids,
    const void*  __restrict__ location_ids,
    float* __restrict__ out,
    int naug,
    int num_procs,
    int num_locs,
    int ntiles)
{
    __shared__ float s_procT[PROC_DIM * 64];                       // [c][pid]
    __shared__ __align__(16) float s_stage[WARPS][2][TILE * OUT_DIM];  // 2x1408B/warp

    const int tid  = threadIdx.x;
    const int warp = tid >> 5;
    const int lane = tid & 31;

    const int proc_elems = num_procs * PROC_DIM;
    for (int i = tid; i < proc_elems; i += THREADS) {
        s_procT[(i % PROC_DIM) * num_procs + (i / PROC_DIM)] = proc_pos[i];
    }
    __syncthreads();

    const int ids64 = g_ids_are_i64;
    const int GW = gridDim.x * WARPS;
    int t = blockIdx.x * WARPS + warp;
    if (t >= ntiles) return;

    // Pipeline prologue (R13 structure).
    int g = load_ids_packed(process_ids, location_ids, t * TILE + lane,
                            naug, ids64, num_procs, num_locs);
    float4 v = __ldcg(&g_locs_pad[g & 0xFFFFF]);

    int tn = t + GW;
    int g_n = 0;
    if (tn < ntiles)
        g_n = load_ids_packed(process_ids, location_ids, tn * TILE + lane,
                              naug, ids64, num_procs, num_locs);

    int sb = 0;   // stage slot for current tile
    while (t < ntiles) {
        // Next tile's gather (ids resident, index clamped -> always safe).
        float4 v_n = __ldcg(&g_locs_pad[g_n & 0xFFFFF]);

        // Ids two tiles ahead.
        const int tnn = tn + GW;
        int g_nn = 0;
        if (tnn < ntiles)
            g_nn = load_ids_packed(process_ids, location_ids, tnn * TILE + lane,
                                   naug, ids64, num_procs, num_locs);

        // Slot sb's bulk store (committed 2 iterations ago) must have
        // finished READING smem before we overwrite. Allow 1 outstanding
        // group (= previous iteration's store of the other slot).
        if (lane == 0)
            asm volatile("cp.async.bulk.wait_group.read 1;" ::: "memory");
        __syncwarp();

        const int rb = t * TILE;
        const int pid = g >> 20;
        float* dst = &s_stage[warp][sb][lane * OUT_DIM];

        if (rb + TILE <= naug) {
            // ---- Full tile ----
            #pragma unroll
            for (int c = 0; c < PROC_DIM; c++)
                dst[c] = s_procT[c * num_procs + pid];
            dst[PROC_DIM + 0] = v.x;
            dst[PROC_DIM + 1] = v.y;
            dst[PROC_DIM + 2] = v.z;
            __syncwarp();

            if (lane == 0) {
                asm volatile("fence.proxy.async.shared::cta;" ::: "memory");
                uint32_t s_addr = (uint32_t)__cvta_generic_to_shared(&s_stage[warp][sb][0]);
                unsigned long long g_addr =
                    (unsigned long long)__cvta_generic_to_global(out + (size_t)rb * OUT_DIM);
                asm volatile(
                    "cp.async.bulk.global.shared::cta.bulk_group [%0], [%1], %2;"
                    :: "l"(g_addr), "r"(s_addr), "r"(TILE_BYTES) : "memory");
                asm volatile("cp.async.bulk.commit_group;" ::: "memory");
            }
        } else {
            // ---- Tail tile (scalar path) ----
            if (rb + lane < naug) {
                #pragma unroll
                for (int c = 0; c < PROC_DIM; c++)
                    dst[c] = s_procT[c * num_procs + pid];
                dst[PROC_DIM + 0] = v.x;
                dst[PROC_DIM + 1] = v.y;
                dst[PROC_DIM + 2] = v.z;
            }
            __syncwarp();
            const int total = (naug - rb) * OUT_DIM;
            float* o = out + (size_t)rb * OUT_DIM;
            const float* st = &s_stage[warp][sb][0];
            for (int i = lane; i < total; i += 32)
                o[i] = st[i];
        }

        // Rotate pipeline.
        g = g_n; v = v_n;
        g_n = g_nn;
        t = tn; tn = tnn;
        sb ^= 1;
    }

    // Drain outstanding bulk stores before exit.
    if (lane == 0)
        asm volatile("cp.async.bulk.wait_group.read 0;" ::: "memory");
}

// Safety fallback for num_locs > MAX_LOCS (not hit for this problem).
__global__ __launch_bounds__(THREADS)
void gather_concat_fallback(
    const float* __restrict__ proc_pos,
    const float* __restrict__ locs_sp,
    const void*  __restrict__ process_ids,
    const void*  __restrict__ location_ids,
    float* __restrict__ out,
    int naug, int num_procs, int num_locs)
{
    const long long row = (long long)blockIdx.x * THREADS + threadIdx.x;
    if (row >= naug) return;
    const int ids64 = g_ids_are_i64;
    long long rp, rl;
    if (ids64) {
        rp = ((const long long*)process_ids)[row];
        rl = ((const long long*)location_ids)[row];
    } else {
        rp = ((const int*)process_ids)[row];
        rl = ((const int*)location_ids)[row];
    }
    int pid = (int)min(max(rp, 0LL), (long long)num_procs - 1);
    long long lid = min(max(rl, 0LL), (long long)num_locs - 1);
    float* o = out + (size_t)row * OUT_DIM;
    #pragma unroll
    for (int c = 0; c < PROC_DIM; c++) o[c] = proc_pos[pid * PROC_DIM + c];
    #pragma unroll
    for (int c = 0; c < SP_DIM; c++)  o[PROC_DIM + c] = locs_sp[lid * SP_DIM + c];
}

extern "C" void kernel_launch(void* const* d_in, const int* in_sizes, int n_in,
                              void* d_out, int out_size) {
    const float* proc_pos     = (const float*)d_in[0];
    const float* locs_sp      = (const float*)d_in[1];
    const void*  process_ids  = d_in[2];
    const void*  location_ids = d_in[3];
    float* out = (float*)d_out;

    const int naug      = in_sizes[2];              // 8,000,000
    const int num_procs = in_sizes[0] / PROC_DIM;   // 16
    const int num_locs  = in_sizes[1] / SP_DIM;     // 500,000

    if (num_locs > MAX_LOCS) {
        setup_kernel<<<1, 256>>>(locs_sp, 0, (const int*)location_ids, naug);
        const long long grid = ((long long)naug + THREADS - 1) / THREADS;
        gather_concat_fallback<<<(int)grid, THREADS>>>(
            proc_pos, locs_sp, process_ids, location_ids, out,
            naug, num_procs, num_locs);
        return;
    }

    {
        const int pg = (num_locs + 255) / 256;
        setup_kernel<<<pg, 256>>>(locs_sp, num_locs,
                                  (const int*)location_ids, naug);
    }

    const int ntiles = (naug + TILE - 1) / TILE;    // 250,000
    long long max_blocks = ((long long)ntiles + WARPS - 1) / WARPS;
    int grid = (int)(max_blocks < 1216 ? max_blocks : 1216);   // 152 SMs x 8
    gather_concat_kernel<<<grid, THREADS>>>(
        proc_pos, process_ids, location_ids, out,
        naug, num_procs, num_locs, ntiles);
}